// round 2
// baseline (speedup 1.0000x reference)
#include <cuda_runtime.h>

// ---------------------------------------------------------------------------
// 5-layer stacked LSTM, H=51, B=256, T=2048.
// Output only depends on layer-3 hidden state => layers 4 and 5 are dead code.
// Persistent layer-pipelined kernel: 3 roles (L1, L2, L3) x 32 batch groups.
// Weights SMEM-resident; h handed between layers via global ring + acq/rel flags.
// ---------------------------------------------------------------------------

#define HN 51
#define NJ 204              // 4*H gate rows
#define BN 256
#define TN 2048
#define NG 32               // batch groups
#define BT 8                // batch per group
#define NSLOT 4             // ring slots (power of 2)
#define NTHREADS 128

// stage 0: L1->L2, stage 1: L2->L3
__device__ float    g_hbuf[2][NG][NSLOT][HN * BT];
__device__ unsigned g_prod[2][NG];
__device__ unsigned g_cons[2][NG];

__device__ __forceinline__ unsigned ld_acq(const unsigned* p) {
    unsigned v;
    asm volatile("ld.global.acquire.gpu.u32 %0, [%1];" : "=r"(v) : "l"(p));
    return v;
}
__device__ __forceinline__ void st_rel(unsigned* p, unsigned v) {
    asm volatile("st.global.release.gpu.u32 [%0], %1;" :: "l"(p), "r"(v));
}
__device__ __forceinline__ void wait_ge(unsigned* p, unsigned v) {
    if (ld_acq(p) >= v) return;
    while (ld_acq(p) < v) __nanosleep(64);
}

__device__ __forceinline__ float sigf(float x) {
    // 1/(1+e^-x); __expf saturates to +inf for large arg, rcp(inf)=0 -> safe.
    return __fdividef(1.f, 1.f + __expf(-x));
}
__device__ __forceinline__ float tanhfast(float x) {
    // tanh(x) = 2*sigmoid(2x) - 1 ; safe at both extremes.
    return 2.f * __fdividef(1.f, 1.f + __expf(-2.f * x)) - 1.f;
}

__global__ void __launch_bounds__(NTHREADS, 1) reset_kernel() {
    int i = threadIdx.x;
    if (i < NG) {
        g_prod[0][i] = 0; g_prod[1][i] = 0;
        g_cons[0][i] = 0; g_cons[1][i] = 0;
    }
}

__global__ void __launch_bounds__(NTHREADS, 1) lstm_kernel(
    const float* __restrict__ x,    const float* __restrict__ Wih1,
    const float* __restrict__ Whh1, const float* __restrict__ bih1,
    const float* __restrict__ bhh1, const float* __restrict__ Wih,
    const float* __restrict__ Whh,  const float* __restrict__ bih,
    const float* __restrict__ bhh,  const float* __restrict__ Wl,
    const float* __restrict__ bl,   float* __restrict__ out)
{
    extern __shared__ float sm[];
    float* wih_t   = sm;            // [51][204] transposed: [k][j]
    float* whh_t   = sm + 10404;    // [51][204]
    float* bias_s  = sm + 20808;    // [204]  bih+bhh
    float* wihv_s  = sm + 21012;    // [204]  L1 rank-1 input weights
    float* xin_t   = sm + 21216;    // [51][8]  layer input (prev layer h)
    float* h_t     = sm + 21624;    // [51][8]
    float* c_s     = sm + 22032;    // [51][8]
    float* gates_s = sm + 22440;    // [204][8]
    float* xchunk  = sm + 24072;    // [8][32] L1 raw-x prefetch
    float* wl_s    = sm + 24328;    // [52]
    // total 24380 floats = 97520 bytes

    const int tid  = threadIdx.x;
    const int bid  = blockIdx.x;
    const int role = bid / NG;      // 0 = L1, 1 = L2, 2 = L3
    const int g    = bid % NG;

    // ---------------- weight load (once) ----------------
    if (role == 0) {
        for (int i = tid; i < NJ; i += NTHREADS) {
            wihv_s[i] = Wih1[i];
            bias_s[i] = bih1[i] + bhh1[i];
        }
        for (int i = tid; i < NJ * HN; i += NTHREADS) {
            int j = i / HN, k = i % HN;
            whh_t[k * NJ + j] = Whh1[i];
        }
    } else {
        const int l = role - 1;               // stacked layer index (0 -> layer2, 1 -> layer3)
        const float* wi = Wih + l * NJ * HN;
        const float* wh = Whh + l * NJ * HN;
        for (int i = tid; i < NJ; i += NTHREADS)
            bias_s[i] = bih[l * NJ + i] + bhh[l * NJ + i];
        for (int i = tid; i < NJ * HN; i += NTHREADS) {
            int j = i / HN, k = i % HN;
            wih_t[k * NJ + j] = wi[i];
            whh_t[k * NJ + j] = wh[i];
        }
        if (role == 2 && tid < HN) wl_s[tid] = Wl[tid];
    }
    for (int i = tid; i < HN * BT; i += NTHREADS) { h_t[i] = 0.f; c_s[i] = 0.f; }
    const float blv = (role == 2) ? bl[0] : 0.f;
    __syncthreads();

    const int  jq     = tid % 51;             // gate-row quad index (4 rows each)
    const int  bq     = tid / 51;             // batch quad index (BT/4 = 2)
    const bool active = (tid < 102);

    float*       hb_out = (role < 2) ? &g_hbuf[role][g][0][0]     : (float*)0;
    const float* hb_in  = (role > 0) ? &g_hbuf[role - 1][g][0][0] : (const float*)0;

    for (int t = 0; t < TN; t++) {
        // --- L1: prefetch a 32-step chunk of raw x (coalesced) ---
        if (role == 0 && (t & 31) == 0) {
            for (int i = tid; i < BT * 32; i += NTHREADS) {
                int b = i >> 5, q = i & 31;
                xchunk[i] = x[(size_t)(g * BT + b) * TN + t + q];
            }
            __syncthreads();
        }

        // ---------------- phase A: bias + input term (L1) + recurrent GEMV ----------------
        float acc[4][4];
        if (active) {
            #pragma unroll
            for (int jj = 0; jj < 4; jj++) {
                float bj = bias_s[4 * jq + jj];
                #pragma unroll
                for (int bb = 0; bb < 4; bb++) acc[jj][bb] = bj;
            }
            if (role == 0) {
                float xv[4];
                #pragma unroll
                for (int jj = 0; jj < 4; jj++) xv[jj] = wihv_s[4 * jq + jj];
                #pragma unroll
                for (int bb = 0; bb < 4; bb++) {
                    float xb = xchunk[(4 * bq + bb) * 32 + (t & 31)];
                    #pragma unroll
                    for (int jj = 0; jj < 4; jj++) acc[jj][bb] += xv[jj] * xb;
                }
            }
            #pragma unroll 3
            for (int k = 0; k < HN; k++) {
                float4 w  = *(const float4*)&whh_t[k * NJ + 4 * jq];
                float4 hv = *(const float4*)&h_t[k * BT + 4 * bq];
                acc[0][0] += w.x * hv.x; acc[0][1] += w.x * hv.y; acc[0][2] += w.x * hv.z; acc[0][3] += w.x * hv.w;
                acc[1][0] += w.y * hv.x; acc[1][1] += w.y * hv.y; acc[1][2] += w.y * hv.z; acc[1][3] += w.y * hv.w;
                acc[2][0] += w.z * hv.x; acc[2][1] += w.z * hv.y; acc[2][2] += w.z * hv.z; acc[2][3] += w.z * hv.w;
                acc[3][0] += w.w * hv.x; acc[3][1] += w.w * hv.y; acc[3][2] += w.w * hv.z; acc[3][3] += w.w * hv.w;
            }
        }

        // ---------------- phase B: wait for upstream h, input GEMV ----------------
        if (role > 0) {
            if (tid == 0) wait_ge(&g_prod[role - 1][g], (unsigned)(t + 1));
            __syncthreads();
            const float* src = hb_in + (t & (NSLOT - 1)) * HN * BT;
            for (int i = tid; i < HN * BT; i += NTHREADS) xin_t[i] = src[i];
            __syncthreads();
            if (tid == 0) st_rel(&g_cons[role - 1][g], (unsigned)(t + 1));
            if (active) {
                #pragma unroll 3
                for (int k = 0; k < HN; k++) {
                    float4 w  = *(const float4*)&wih_t[k * NJ + 4 * jq];
                    float4 xv = *(const float4*)&xin_t[k * BT + 4 * bq];
                    acc[0][0] += w.x * xv.x; acc[0][1] += w.x * xv.y; acc[0][2] += w.x * xv.z; acc[0][3] += w.x * xv.w;
                    acc[1][0] += w.y * xv.x; acc[1][1] += w.y * xv.y; acc[1][2] += w.y * xv.z; acc[1][3] += w.y * xv.w;
                    acc[2][0] += w.z * xv.x; acc[2][1] += w.z * xv.y; acc[2][2] += w.z * xv.z; acc[2][3] += w.z * xv.w;
                    acc[3][0] += w.w * xv.x; acc[3][1] += w.w * xv.y; acc[3][2] += w.w * xv.z; acc[3][3] += w.w * xv.w;
                }
            }
        }

        // ---------------- phase C: spill gates to SMEM ----------------
        if (active) {
            #pragma unroll
            for (int jj = 0; jj < 4; jj++)
                #pragma unroll
                for (int bb = 0; bb < 4; bb++)
                    gates_s[(4 * jq + jj) * BT + (4 * bq + bb)] = acc[jj][bb];
        }
        // backpressure: don't overwrite a ring slot the consumer hasn't read
        if (role < 2 && t >= NSLOT && tid == 0)
            wait_ge(&g_cons[role][g], (unsigned)(t - NSLOT + 1));
        __syncthreads();

        // ---------------- phase D: cell update ----------------
        float* hb_dst = (role < 2) ? (hb_out + (t & (NSLOT - 1)) * HN * BT) : (float*)0;
        for (int i = tid; i < HN * BT; i += NTHREADS) {
            float gi = gates_s[i];
            float gf = gates_s[HN * BT + i];
            float gg = gates_s[2 * HN * BT + i];
            float go = gates_s[3 * HN * BT + i];
            float c  = sigf(gf) * c_s[i] + sigf(gi) * tanhfast(gg);
            float h  = sigf(go) * tanhfast(c);
            c_s[i] = c;
            h_t[i] = h;
            if (role < 2) hb_dst[i] = h;
        }
        __syncthreads();
        if (role < 2 && tid == 0) st_rel(&g_prod[role][g], (unsigned)(t + 1));

        // ---------------- phase E: output projection from layer-3 h ----------------
        if (role == 2 && tid < BT) {
            float a = blv;
            #pragma unroll
            for (int u = 0; u < HN; u++) a += h_t[u * BT + tid] * wl_s[u];
            out[(size_t)(g * BT + tid) * TN + t] = a;
        }
    }
}

extern "C" void kernel_launch(void* const* d_in, const int* in_sizes, int n_in,
                              void* d_out, int out_size)
{
    (void)in_sizes; (void)n_in; (void)out_size;
    const float* x    = (const float*)d_in[0];
    const float* Wih1 = (const float*)d_in[1];
    const float* Whh1 = (const float*)d_in[2];
    const float* bih1 = (const float*)d_in[3];
    const float* bhh1 = (const float*)d_in[4];
    const float* Wih  = (const float*)d_in[5];
    const float* Whh  = (const float*)d_in[6];
    const float* bih  = (const float*)d_in[7];
    const float* bhh  = (const float*)d_in[8];
    const float* Wl   = (const float*)d_in[9];
    const float* bl   = (const float*)d_in[10];
    float* out = (float*)d_out;

    const int smem_bytes = 24380 * 4;  // 97520
    cudaFuncSetAttribute(lstm_kernel, cudaFuncAttributeMaxDynamicSharedMemorySize, smem_bytes);

    reset_kernel<<<1, NTHREADS>>>();
    lstm_kernel<<<3 * NG, NTHREADS, smem_bytes>>>(
        x, Wih1, Whh1, bih1, bhh1, Wih, Whh, bih, bhh, Wl, bl, out);
}

// round 3
// speedup vs baseline: 1.8578x; 1.8578x over previous
#include <cuda_runtime.h>

// ---------------------------------------------------------------------------
// 5-layer stacked LSTM, H=51, B=256, T=2048. Output depends only on layer-3 h
// => layers 4,5 dead. 3 roles (L1,L2,L3) x 32 batch groups = 96 CTAs.
// Per-thread register-resident weights (1 gate row / thread), f32x2 packed FMA,
// warp-7-specialized inter-layer copy + flags, double-buffered layer input.
// ---------------------------------------------------------------------------

#define HN 51
#define NJ 204
#define TN 2048
#define NG 32
#define BT 8
#define NSLOT 8
#define NTH 256

typedef unsigned long long ull;

__device__ float    g_hbuf[2][NG][NSLOT][HN * BT];
__device__ unsigned g_prod[2][NG];
__device__ unsigned g_cons[2][NG];

__device__ __forceinline__ unsigned ld_acq(const unsigned* p) {
    unsigned v;
    asm volatile("ld.global.acquire.gpu.u32 %0, [%1];" : "=r"(v) : "l"(p));
    return v;
}
__device__ __forceinline__ void st_rel(unsigned* p, unsigned v) {
    asm volatile("st.global.release.gpu.u32 [%0], %1;" :: "l"(p), "r"(v));
}
__device__ __forceinline__ void wait_ge(unsigned* p, unsigned v) {
    while (ld_acq(p) < v) { }
}
__device__ __forceinline__ float ldcg(const float* p) {
    float v;
    asm volatile("ld.global.cg.f32 %0, [%1];" : "=f"(v) : "l"(p));
    return v;
}
__device__ __forceinline__ ull ffma2(ull a, ull b, ull c) {
    ull d;
    asm("fma.rn.f32x2 %0, %1, %2, %3;" : "=l"(d) : "l"(a), "l"(b), "l"(c));
    return d;
}
__device__ __forceinline__ ull splat2(float x) {
    ull d; unsigned u = __float_as_uint(x);
    asm("mov.b64 %0, {%1, %2};" : "=l"(d) : "r"(u), "r"(u));
    return d;
}
__device__ __forceinline__ float sigf(float x) {
    return __fdividef(1.f, 1.f + __expf(-x));
}
__device__ __forceinline__ float tanhfast(float x) {
    return 2.f * __fdividef(1.f, 1.f + __expf(-2.f * x)) - 1.f;
}

__global__ void __launch_bounds__(NTH, 1) reset_kernel() {
    int i = threadIdx.x;
    if (i < NG) {
        g_prod[0][i] = 0; g_prod[1][i] = 0;
        g_cons[0][i] = 0; g_cons[1][i] = 0;
    }
}

__global__ void __launch_bounds__(NTH, 1) lstm_kernel(
    const float* __restrict__ x,    const float* __restrict__ Wih1,
    const float* __restrict__ Whh1, const float* __restrict__ bih1,
    const float* __restrict__ bhh1, const float* __restrict__ Wih,
    const float* __restrict__ Whh,  const float* __restrict__ bih,
    const float* __restrict__ bhh,  const float* __restrict__ Wl,
    const float* __restrict__ bl,   float* __restrict__ out)
{
    __shared__ __align__(16) float xin[2][HN * BT];   // layer input double buffer
    __shared__ __align__(16) float h_t[HN * BT];
    __shared__ __align__(16) float c_s[HN * BT];
    __shared__ __align__(16) float gates[4 * HN * BT];
    __shared__ __align__(16) float xchunk[32 * BT];   // [q][b], L1 raw-x prefetch
    __shared__ float wl_s[52];

    const int tid  = threadIdx.x;
    const int role = blockIdx.x / NG;   // 0=L1, 1=L2, 2=L3
    const int g    = blockIdx.x % NG;
    const int j    = tid;               // gate row (tid < 204)

    // ---------------- per-thread register weights ----------------
    float whh_r[HN];
    float wih_r[HN];
    ull bias2 = 0, w1_2 = 0;
    if (tid < NJ) {
        if (role == 0) {
            #pragma unroll
            for (int k = 0; k < HN; k++) whh_r[k] = Whh1[j * HN + k];
            bias2 = splat2(bih1[j] + bhh1[j]);
            w1_2  = splat2(Wih1[j]);
        } else {
            const int l = role - 1;
            #pragma unroll
            for (int k = 0; k < HN; k++) whh_r[k] = Whh[(l * NJ + j) * HN + k];
            #pragma unroll
            for (int k = 0; k < HN; k++) wih_r[k] = Wih[(l * NJ + j) * HN + k];
            bias2 = splat2(bih[l * NJ + j] + bhh[l * NJ + j]);
        }
    }
    if (role == 2 && tid < HN) wl_s[tid] = Wl[tid];
    const float blv = (role == 2) ? bl[0] : 0.f;
    for (int i = tid; i < HN * BT; i += NTH) { h_t[i] = 0.f; c_s[i] = 0.f; }
    __syncthreads();

    float*       ring_out = (role < 2) ? &g_hbuf[role][g][0][0]     : (float*)0;
    const float* ring_in  = (role > 0) ? &g_hbuf[role - 1][g][0][0] : (const float*)0;

    // prologue: warp 7 fetches slot 0 -> xin[0]
    if (role > 0 && tid >= 224) {
        if (tid == 224) wait_ge(&g_prod[role - 1][g], 1u);
        __syncwarp();
        for (int i = tid - 224; i < HN * BT; i += 32) xin[0][i] = ldcg(ring_in + i);
        __syncwarp();
        if (tid == 224) st_rel(&g_cons[role - 1][g], 1u);
    }
    __syncthreads();

    for (int t = 0; t < TN; t++) {
        // ---- L1: refill 32-step x chunk (coalesced), transposed [q][b] ----
        if (role == 0 && (t & 31) == 0) {
            int b = tid >> 5, q = tid & 31;
            xchunk[q * BT + b] = x[(size_t)(g * BT + b) * TN + t + q];
            __syncthreads();
        }

        // ================= P0 =================
        if (tid < NJ) {
            ull a0 = bias2, a1 = bias2, a2 = bias2, a3 = bias2;
            if (role == 0) {
                const ulonglong2* xp = (const ulonglong2*)&xchunk[(t & 31) * BT];
                ulonglong2 X0 = xp[0], X1 = xp[1];
                a0 = ffma2(X0.x, w1_2, a0); a1 = ffma2(X0.y, w1_2, a1);
                a2 = ffma2(X1.x, w1_2, a2); a3 = ffma2(X1.y, w1_2, a3);
            } else {
                const ulonglong2* xp = (const ulonglong2*)&xin[t & 1][0];
                #pragma unroll
                for (int k = 0; k < HN; k++) {
                    ulonglong2 X0 = xp[2 * k], X1 = xp[2 * k + 1];
                    ull w2 = splat2(wih_r[k]);
                    a0 = ffma2(X0.x, w2, a0); a1 = ffma2(X0.y, w2, a1);
                    a2 = ffma2(X1.x, w2, a2); a3 = ffma2(X1.y, w2, a3);
                }
            }
            const ulonglong2* hp = (const ulonglong2*)h_t;
            #pragma unroll
            for (int k = 0; k < HN; k++) {
                ulonglong2 H0 = hp[2 * k], H1 = hp[2 * k + 1];
                ull w2 = splat2(whh_r[k]);
                a0 = ffma2(H0.x, w2, a0); a1 = ffma2(H0.y, w2, a1);
                a2 = ffma2(H1.x, w2, a2); a3 = ffma2(H1.y, w2, a3);
            }
            ulonglong2* gp = (ulonglong2*)gates;
            ulonglong2 s0; s0.x = a0; s0.y = a1;
            ulonglong2 s1; s1.x = a2; s1.y = a3;
            gp[j * 2 + 0] = s0;
            gp[j * 2 + 1] = s1;
        } else if (tid >= 224) {
            // warp 7: communication + (L3) output projection, hidden under GEMVs
            if (role > 0 && t + 1 < TN) {
                if (tid == 224) wait_ge(&g_prod[role - 1][g], (unsigned)(t + 2));
                __syncwarp();
                const float* src = ring_in + ((t + 1) & (NSLOT - 1)) * HN * BT;
                float* dst = xin[(t + 1) & 1];
                for (int i = tid - 224; i < HN * BT; i += 32) dst[i] = ldcg(src + i);
                __syncwarp();
                if (tid == 224) st_rel(&g_cons[role - 1][g], (unsigned)(t + 2));
            }
            if (role < 2 && t >= NSLOT && tid == 224)
                wait_ge(&g_cons[role][g], (unsigned)(t - (NSLOT - 1)));
            if (role == 2 && t > 0) {
                int b = tid - 224;
                if (b < BT) {
                    float a = blv;
                    #pragma unroll
                    for (int u = 0; u < HN; u++) a += h_t[u * BT + b] * wl_s[u];
                    out[(size_t)(g * BT + b) * TN + (t - 1)] = a;
                }
            }
        }
        __syncthreads();   // sync1: gates ready, h_t free, backpressure cleared

        // ================= P1: cell update =================
        {
            float* hb = (role < 2) ? ring_out + (t & (NSLOT - 1)) * HN * BT : (float*)0;
            for (int i = tid; i < HN * BT; i += NTH) {
                float gi = gates[i];
                float gf = gates[HN * BT + i];
                float gg = gates[2 * HN * BT + i];
                float go = gates[3 * HN * BT + i];
                float c  = sigf(gf) * c_s[i] + sigf(gi) * tanhfast(gg);
                float h  = sigf(go) * tanhfast(c);
                c_s[i] = c;
                h_t[i] = h;
                if (role < 2) hb[i] = h;
            }
        }
        __syncthreads();   // sync2: h_t / ring slot complete
        if (role < 2 && tid == 0) st_rel(&g_prod[role][g], (unsigned)(t + 1));
    }

    // epilogue: out for t = TN-1 (from final h_t of layer 3)
    if (role == 2 && tid < BT) {
        float a = blv;
        #pragma unroll
        for (int u = 0; u < HN; u++) a += h_t[u * BT + tid] * wl_s[u];
        out[(size_t)(g * BT + tid) * TN + (TN - 1)] = a;
    }
}

extern "C" void kernel_launch(void* const* d_in, const int* in_sizes, int n_in,
                              void* d_out, int out_size)
{
    (void)in_sizes; (void)n_in; (void)out_size;
    const float* x    = (const float*)d_in[0];
    const float* Wih1 = (const float*)d_in[1];
    const float* Whh1 = (const float*)d_in[2];
    const float* bih1 = (const float*)d_in[3];
    const float* bhh1 = (const float*)d_in[4];
    const float* Wih  = (const float*)d_in[5];
    const float* Whh  = (const float*)d_in[6];
    const float* bih  = (const float*)d_in[7];
    const float* bhh  = (const float*)d_in[8];
    const float* Wl   = (const float*)d_in[9];
    const float* bl   = (const float*)d_in[10];
    float* out = (float*)d_out;

    reset_kernel<<<1, NTH>>>();
    lstm_kernel<<<3 * NG, NTH>>>(x, Wih1, Whh1, bih1, bhh1,
                                 Wih, Whh, bih, bhh, Wl, bl, out);
}